// round 14
// baseline (speedup 1.0000x reference)
#include <cuda_runtime.h>
#include <math.h>

#define B 2
#define C 32
#define O 32
#define N 64
#define M 20
#define MM 400
#define MMM 8000
#define NN 4096

// Scratch (bss, allocation-free)
__device__ float g_Y2[(size_t)B * C * N * MM];   // fwd Y2 [bc][d][m]; reused as U1 [bo][d][m]
__device__ float g_Y3[(size_t)B * C * MMM];      // [bc][kd][m]
__device__ float g_Zp[4][(size_t)B * O * MMM];   // 4 c-partial sums of Z

#define PI_F 3.14159265358979323846f

// ---------------------------------------------------------------------------
// Compile-time DCT coefficients (folded to FFMA immediates, rt_SMSP=1)
// ---------------------------------------------------------------------------
__host__ __device__ constexpr double tcos(int a) {      // cos(pi*a/128)
    double x = 3.14159265358979323846264338327950288 * (double)a / 128.0;
    double x2 = x * x, term = 1.0, s = 1.0;
    for (int i = 1; i <= 16; i++) { term *= -x2 / (double)((2 * i - 1) * (2 * i)); s += term; }
    return s;
}
__host__ __device__ constexpr int redu(int k, int n) {
    int a = (k * (2 * n + 1)) % 256;
    return (a > 128) ? 256 - a : a;
}
__host__ __device__ constexpr float CF(int n, int k) {  // forward DCT-II coeff
    double c = tcos(redu(k, n));
    return (k == 0) ? 1.0f : (float)(2.0 * c);
}
__host__ __device__ constexpr float CI(int n, int k) {  // inverse DCT-III coeff
    double c = tcos(redu(k, n));
    return (float)(((k == 0) ? 1.0 : c) / 64.0);
}

template<int I> struct ic { static constexpr int value = I; };
template<int I, int Nn> struct SF {
    template<class F> __device__ __forceinline__ static void run(F&& f) {
        f(ic<I>{}); SF<I + 1, Nn>::run(f);
    }
};
template<int Nn> struct SF<Nn, Nn> {
    template<class F> __device__ __forceinline__ static void run(F&&) {}
};
template<int Nn, class F> __device__ __forceinline__ void static_for(F&& f) { SF<0, Nn>::run(f); }

// cp.async helpers
__device__ __forceinline__ unsigned smem_u32(const void* p) {
    return (unsigned)__cvta_generic_to_shared(p);
}
__device__ __forceinline__ void cp_async16(unsigned dst, const void* src, int szbytes) {
    asm volatile("cp.async.cg.shared.global [%0], [%1], 16, %2;\n"
                 :: "r"(dst), "l"(src), "r"(szbytes));
}
__device__ __forceinline__ void cp_async_wait_all() {
    asm volatile("cp.async.commit_group;\n");
    asm volatile("cp.async.wait_group 0;\n");
}

// ---------------------------------------------------------------------------
// fwd_wh: x[slice][h][w] -> Y2[slice][kh][kw], 1 slice per 128-thread block.
// ---------------------------------------------------------------------------
template<int KW0>
__device__ __forceinline__ void fwd_s1(const float* __restrict__ xr, float* __restrict__ tT, int h) {
    float acc[10];
#pragma unroll
    for (int k = 0; k < 10; k++) acc[k] = 0.f;
    static_for<8>([&](auto W4) {
        constexpr int w4 = W4.value;
        float4 av = *(const float4*)(xr + w4 * 4);
        float4 bv = *(const float4*)(xr + 60 - w4 * 4);
        float s0 = av.x + bv.w, d0 = av.x - bv.w;
        float s1 = av.y + bv.z, d1 = av.y - bv.z;
        float s2 = av.z + bv.y, d2 = av.z - bv.y;
        float s3 = av.w + bv.x, d3 = av.w - bv.x;
        static_for<10>([&](auto K) {
            constexpr int k = K.value;
            constexpr int kw = KW0 + k;
            constexpr float c0 = CF(w4 * 4 + 0, kw);
            constexpr float c1 = CF(w4 * 4 + 1, kw);
            constexpr float c2 = CF(w4 * 4 + 2, kw);
            constexpr float c3 = CF(w4 * 4 + 3, kw);
            if constexpr (kw & 1) {
                acc[k] += d0 * c0; acc[k] += d1 * c1;
                acc[k] += d2 * c2; acc[k] += d3 * c3;
            } else {
                acc[k] += s0 * c0; acc[k] += s1 * c1;
                acc[k] += s2 * c2; acc[k] += s3 * c3;
            }
        });
    });
#pragma unroll
    for (int k = 0; k < 10; k++) tT[(KW0 + k) * 68 + h] = acc[k];
}

template<int KH0>
__device__ __forceinline__ void fwd_s2(const float* __restrict__ trow, float* __restrict__ outp, bool act) {
    float acc[5] = {0.f, 0.f, 0.f, 0.f, 0.f};
    static_for<8>([&](auto H4) {
        constexpr int h4 = H4.value;
        float4 av = *(const float4*)(trow + h4 * 4);
        float4 bv = *(const float4*)(trow + 60 - h4 * 4);
        float s0 = av.x + bv.w, d0 = av.x - bv.w;
        float s1 = av.y + bv.z, d1 = av.y - bv.z;
        float s2 = av.z + bv.y, d2 = av.z - bv.y;
        float s3 = av.w + bv.x, d3 = av.w - bv.x;
        static_for<5>([&](auto K) {
            constexpr int k = K.value;
            constexpr int kh = KH0 + k;
            constexpr float c0 = CF(h4 * 4 + 0, kh);
            constexpr float c1 = CF(h4 * 4 + 1, kh);
            constexpr float c2 = CF(h4 * 4 + 2, kh);
            constexpr float c3 = CF(h4 * 4 + 3, kh);
            if constexpr (kh & 1) {
                acc[k] += d0 * c0; acc[k] += d1 * c1;
                acc[k] += d2 * c2; acc[k] += d3 * c3;
            } else {
                acc[k] += s0 * c0; acc[k] += s1 * c1;
                acc[k] += s2 * c2; acc[k] += s3 * c3;
            }
        });
    });
    if (act) {
#pragma unroll
        for (int k = 0; k < 5; k++) outp[(KH0 + k) * 20] = acc[k];
    }
}

__global__ __launch_bounds__(128) void fwd_wh_k(const float* __restrict__ x, int slice0) {
    __shared__ float xs[64 * 68];         // [h][w], stride 68
    __shared__ float tT[20 * 68];         // [kw][h], stride 68
    int t = threadIdx.x, wid = t >> 5, lane = t & 31;
    int slice = slice0 + blockIdx.x;
    const float* xp = x + (size_t)slice * NN;
#pragma unroll
    for (int r = 0; r < 8; r++) {
        int idx = t + r * 128;            // float4 index 0..1023
        int h = idx >> 4, w4 = idx & 15;
        *(float4*)&xs[h * 68 + w4 * 4] = *(const float4*)(xp + idx * 4);
    }
    __syncthreads();
    {   // stage 1: tT[kw][h] = sum_w xs[h][w]*CF(w,kw)   (butterfly)
        int h = (wid >> 1) * 32 + lane;
        const float* xr = &xs[h * 68];
        if (wid & 1) fwd_s1<10>(xr, tT, h); else fwd_s1<0>(xr, tT, h);
    }
    __syncthreads();
    {   // stage 2: Y2[kh][kw] = sum_h CF(h,kh)*tT[kw][h]  (butterfly, LDS.128)
        bool act = lane < 20;
        int kwc = act ? lane : 0;
        const float* trow = &tT[kwc * 68];
        float* outp = g_Y2 + (size_t)slice * MM + kwc;
        switch (wid) {
            case 0: fwd_s2<0>(trow, outp, act); break;
            case 1: fwd_s2<5>(trow, outp, act); break;
            case 2: fwd_s2<10>(trow, outp, act); break;
            default: fwd_s2<15>(trow, outp, act); break;
        }
    }
}

// ---------------------------------------------------------------------------
// fwd_d: Y2[bc][d][m] -> Y3[bc][kd][m]
// grid (32 bc, 4 mtile100, 4 kdtile5), block 128. 1024 blocks/half for occupancy.
// ---------------------------------------------------------------------------
__global__ __launch_bounds__(128) void fwd_d_k(int bc0) {
    __shared__ float slab[64 * 100];      // [d][m] 12.8 KB
    __shared__ float cfs[64 * 5];         // [d][kdl]
    int bc = bc0 + blockIdx.x, mt = blockIdx.y, kdt = blockIdx.z;
    int t = threadIdx.x;
    const float* src = g_Y2 + (size_t)bc * (N * MM) + mt * 100;
    for (int i = t; i < 1600; i += 128) {
        int d = i / 25, j = (i % 25) * 4;
        *(float4*)&slab[d * 100 + j] = *(const float4*)(src + (size_t)d * MM + j);
    }
    for (int i = t; i < 320; i += 128) {
        int d = i / 5, kl = i % 5;
        int kd = kdt * 5 + kl;
        cfs[i] = (kd == 0) ? 1.0f : 2.0f * cosf(PI_F * (float)(kd * (2 * d + 1)) / 128.0f);
    }
    __syncthreads();
    if (t < 125) {
        int kl = t / 25, f4m = (t % 25) * 4;
        float4 acc = make_float4(0.f, 0.f, 0.f, 0.f);
#pragma unroll 8
        for (int d = 0; d < 64; d++) {
            float c = cfs[d * 5 + kl];
            float4 v = *(const float4*)&slab[d * 100 + f4m];
            acc.x += c * v.x; acc.y += c * v.y; acc.z += c * v.z; acc.w += c * v.w;
        }
        *(float4*)(g_Y3 + (size_t)bc * MMM + (size_t)(kdt * 5 + kl) * MM + mt * 100 + f4m) = acc;
    }
}

// ---------------------------------------------------------------------------
// mix: partial Z over 8 channels per block, cp.async staged, plain stores.
// grid (63 m-tiles of 128, 8 o-tiles of 4, 4 c-quarters), block 128.
// ---------------------------------------------------------------------------
__global__ __launch_bounds__(128) void mix_k(const float* __restrict__ w) {
    __shared__ float ys[2 * 8 * 128];     // 8 KB
    __shared__ float ws[8 * 4 * 128];     // 16 KB
    int mbase = blockIdx.x * 128;
    int o0 = blockIdx.y * 4;
    int c0 = blockIdx.z * 8;
    int t = threadIdx.x, wid = t >> 5, lane = t & 31;
#pragma unroll
    for (int r = 0; r < 4; r++) {         // ys: 512 float4
        int i = t + r * 128;
        int b = i >> 8, c = (i >> 5) & 7, m4 = i & 31;
        int m = mbase + m4 * 4;
        const float* src = g_Y3 + (size_t)(b * C + c0 + c) * MMM + ((m < MMM) ? m : 0);
        cp_async16(smem_u32(&ys[(b * 8 + c) * 128 + m4 * 4]), src, (m < MMM) ? 16 : 0);
    }
#pragma unroll
    for (int r = 0; r < 8; r++) {         // ws: 1024 float4
        int i = t + r * 128;
        int c = i >> 7, ol = (i >> 5) & 3, m4 = i & 31;
        int m = mbase + m4 * 4;
        const float* src = w + ((size_t)(c0 + c) * O + o0 + ol) * MMM + ((m < MMM) ? m : 0);
        cp_async16(smem_u32(&ws[(c * 4 + ol) * 128 + m4 * 4]), src, (m < MMM) ? 16 : 0);
    }
    cp_async_wait_all();
    __syncthreads();
    int o = o0 + wid;
    int m0 = mbase + lane * 4;
    float4 a0 = make_float4(0.f,0.f,0.f,0.f), a1 = a0;
#pragma unroll
    for (int c = 0; c < 8; c++) {
        float4 wv = *(const float4*)&ws[(c * 4 + wid) * 128 + lane * 4];
        float4 y0 = *(const float4*)&ys[c * 128 + lane * 4];
        float4 y1 = *(const float4*)&ys[(8 + c) * 128 + lane * 4];
        a0.x += y0.x*wv.x; a0.y += y0.y*wv.y; a0.z += y0.z*wv.z; a0.w += y0.w*wv.w;
        a1.x += y1.x*wv.x; a1.y += y1.y*wv.y; a1.z += y1.z*wv.z; a1.w += y1.w*wv.w;
    }
    if (m0 < MMM) {
        float* Zp = g_Zp[blockIdx.z];
        *(float4*)(Zp + (size_t)o * MMM + m0) = a0;
        *(float4*)(Zp + (size_t)(O + o) * MMM + m0) = a1;
    }
}

// ---------------------------------------------------------------------------
// inv_d: sum(Zp)[bo][kd][m] -> U1[bo][d][m] (into g_Y2)
// grid (32 bo, 4 mtile100, 4 dtile16), block 128 (100 active: 4 d x 25 f4 each).
// ---------------------------------------------------------------------------
__global__ __launch_bounds__(128) void inv_d_k(int bo0) {
    __shared__ float zs[M * 100];     // [kd][ml] summed tile, 8 KB
    __shared__ float cis[M * 16];     // [kd][dl] for this block's 16 d
    int bo = bo0 + blockIdx.x;
    int mbase = blockIdx.y * 100;
    int dbase = blockIdx.z * 16;
    int t = threadIdx.x;
    const float* p0 = g_Zp[0] + (size_t)bo * MMM + mbase;
    const float* p1 = g_Zp[1] + (size_t)bo * MMM + mbase;
    const float* p2 = g_Zp[2] + (size_t)bo * MMM + mbase;
    const float* p3 = g_Zp[3] + (size_t)bo * MMM + mbase;
    for (int i = t; i < 500; i += 128) {              // 500 float4 = 20 kd x 25
        int kd = i / 25, j = (i % 25) * 4;
        size_t off = (size_t)kd * MM + j;
        float4 a = *(const float4*)(p0 + off);
        float4 b = *(const float4*)(p1 + off);
        float4 c = *(const float4*)(p2 + off);
        float4 d = *(const float4*)(p3 + off);
        a.x += b.x + c.x + d.x; a.y += b.y + c.y + d.y;
        a.z += b.z + c.z + d.z; a.w += b.w + c.w + d.w;
        *(float4*)&zs[kd * 100 + j] = a;
    }
    for (int i = t; i < M * 16; i += 128) {
        int kd = i / 16, dl = i % 16;
        int d = dbase + dl;
        float v = (kd == 0) ? 1.0f : cosf(PI_F * (float)(kd * (2 * d + 1)) / 128.0f);
        cis[i] = v * (1.0f / 64.0f);
    }
    __syncthreads();
    if (t < 100) {
        int dg = t / 25, f4m = (t % 25) * 4;          // dg: 4 groups of 4 d
        float4 acc[4];
#pragma unroll
        for (int i = 0; i < 4; i++) acc[i] = make_float4(0.f,0.f,0.f,0.f);
#pragma unroll
        for (int kd = 0; kd < M; kd++) {
            float4 v = *(const float4*)&zs[kd * 100 + f4m];
            float4 c = *(const float4*)&cis[kd * 16 + dg * 4];
            acc[0].x += c.x*v.x; acc[0].y += c.x*v.y; acc[0].z += c.x*v.z; acc[0].w += c.x*v.w;
            acc[1].x += c.y*v.x; acc[1].y += c.y*v.y; acc[1].z += c.y*v.z; acc[1].w += c.y*v.w;
            acc[2].x += c.z*v.x; acc[2].y += c.z*v.y; acc[2].z += c.z*v.z; acc[2].w += c.z*v.w;
            acc[3].x += c.w*v.x; acc[3].y += c.w*v.y; acc[3].z += c.w*v.z; acc[3].w += c.w*v.w;
        }
        float* q = g_Y2 + (size_t)bo * (N * MM) + mbase + f4m;
#pragma unroll
        for (int i = 0; i < 4; i++)
            *(float4*)(q + (size_t)(dbase + dg * 4 + i) * MM) = acc[i];
    }
}

// ---------------------------------------------------------------------------
// inv_hw: U1[slice][kh][kw] -> out[slice][h][w], 1 slice per 128-thread block.
// tmp stride 28 -> conflict-free LDS.128.
// ---------------------------------------------------------------------------
template<int HB>
__device__ __forceinline__ void inv_s1(const float* __restrict__ zcol, float* __restrict__ tcol, bool act) {
    float E[8], Od[8];
#pragma unroll
    for (int i = 0; i < 8; i++) { E[i] = 0.f; Od[i] = 0.f; }
    static_for<20>([&](auto KH) {
        constexpr int kh = KH.value;
        float zv = zcol[kh * 20];
        static_for<8>([&](auto I) {
            constexpr int i = I.value;
            constexpr float c = CI(HB + i, kh);
            if constexpr (kh & 1) Od[i] += zv * c; else E[i] += zv * c;
        });
    });
    if (act) {
#pragma unroll
        for (int i = 0; i < 8; i++) {
            tcol[(HB + i) * 28] = E[i] + Od[i];
            tcol[(63 - HB - i) * 28] = E[i] - Od[i];
        }
    }
}

template<int W0>
__device__ __forceinline__ void inv_s2(const float* __restrict__ trow, float* __restrict__ orow) {
    float E[16], Od[16];
#pragma unroll
    for (int i = 0; i < 16; i++) { E[i] = 0.f; Od[i] = 0.f; }
    static_for<5>([&](auto K4) {
        constexpr int k4 = K4.value;
        float4 tv = *(const float4*)(trow + k4 * 4);
        float tvv[4] = {tv.x, tv.y, tv.z, tv.w};
        static_for<4>([&](auto J) {
            constexpr int j = J.value;
            constexpr int kw = k4 * 4 + j;
            float tvj = tvv[j];
            static_for<16>([&](auto I) {
                constexpr int i = I.value;
                constexpr float c = CI(W0 + i, kw);
                if constexpr (kw & 1) Od[i] += tvj * c; else E[i] += tvj * c;
            });
        });
    });
#pragma unroll
    for (int j = 0; j < 4; j++) {
        float4 v = make_float4(E[j*4+0] + Od[j*4+0], E[j*4+1] + Od[j*4+1],
                               E[j*4+2] + Od[j*4+2], E[j*4+3] + Od[j*4+3]);
        *(float4*)(orow + W0 + j * 4) = v;
    }
#pragma unroll
    for (int j = 0; j < 4; j++) {
        float4 v = make_float4(E[15-(j*4+0)] - Od[15-(j*4+0)], E[15-(j*4+1)] - Od[15-(j*4+1)],
                               E[15-(j*4+2)] - Od[15-(j*4+2)], E[15-(j*4+3)] - Od[15-(j*4+3)]);
        *(float4*)(orow + (48 - W0) + j * 4) = v;
    }
}

__global__ __launch_bounds__(128) void inv_hw_k(float* __restrict__ out, int slice0) {
    __shared__ float zs[MM];
    __shared__ float tmp[64 * 28];
    int t = threadIdx.x, wid = t >> 5, lane = t & 31;
    int slice = slice0 + blockIdx.x;
    const float* p = g_Y2 + (size_t)slice * MM;
    for (int i = t; i < MM; i += 128) zs[i] = p[i];
    __syncthreads();
    {   // stage 1 (butterfly)
        bool act = lane < 20;
        int kwc = act ? lane : 0;
        const float* zcol = &zs[kwc];
        float* tcol = &tmp[kwc];
        switch (wid) {
            case 0: inv_s1<0>(zcol, tcol, act); break;
            case 1: inv_s1<8>(zcol, tcol, act); break;
            case 2: inv_s1<16>(zcol, tcol, act); break;
            default: inv_s1<24>(zcol, tcol, act); break;
        }
    }
    __syncthreads();
    {   // stage 2 (butterfly), direct gmem stores
        int h = (wid & 1) * 32 + lane;
        const float* trow = &tmp[h * 28];
        float* orow = out + (size_t)slice * NN + h * 64;
        if (wid >> 1) inv_s2<16>(trow, orow); else inv_s2<0>(trow, orow);
    }
}

// ---------------------------------------------------------------------------
// Streams/events created at static init, reused every call.
// ---------------------------------------------------------------------------
struct GraphRes {
    cudaStream_t sA, sB;
    cudaEvent_t eRoot, eB1, eMix, eA2, eB2;
    GraphRes() {
        cudaStreamCreateWithFlags(&sA, cudaStreamNonBlocking);
        cudaStreamCreateWithFlags(&sB, cudaStreamNonBlocking);
        cudaEventCreateWithFlags(&eRoot, cudaEventDisableTiming);
        cudaEventCreateWithFlags(&eB1, cudaEventDisableTiming);
        cudaEventCreateWithFlags(&eMix, cudaEventDisableTiming);
        cudaEventCreateWithFlags(&eA2, cudaEventDisableTiming);
        cudaEventCreateWithFlags(&eB2, cudaEventDisableTiming);
    }
};
static GraphRes g_r;

extern "C" void kernel_launch(void* const* d_in, const int* in_sizes, int n_in,
                              void* d_out, int out_size) {
    const float* x = (const float*)d_in[0];       // (2,32,64,64,64)
    const float* w = (const float*)d_in[1];       // (32,32,20,20,20)
    float* out = (float*)d_out;                   // (2,32,64,64,64)

    // fork from the (captured) legacy stream
    cudaEventRecord(g_r.eRoot, 0);
    cudaStreamWaitEvent(g_r.sA, g_r.eRoot, 0);
    cudaStreamWaitEvent(g_r.sB, g_r.eRoot, 0);

    // forward: two independent bc-halves
    fwd_wh_k<<<2048, 128, 0, g_r.sA>>>(x, 0);
    fwd_d_k<<<dim3(32, 4, 4), 128, 0, g_r.sA>>>(0);
    fwd_wh_k<<<2048, 128, 0, g_r.sB>>>(x, 2048);
    fwd_d_k<<<dim3(32, 4, 4), 128, 0, g_r.sB>>>(32);
    cudaEventRecord(g_r.eB1, g_r.sB);
    cudaStreamWaitEvent(g_r.sA, g_r.eB1, 0);      // join for mix

    mix_k<<<dim3(63, 8, 4), 128, 0, g_r.sA>>>(w);
    cudaEventRecord(g_r.eMix, g_r.sA);
    cudaStreamWaitEvent(g_r.sB, g_r.eMix, 0);

    // inverse: two independent bo-halves (inv_d_B overlaps inv_hw_A)
    inv_d_k<<<dim3(32, 4, 4), 128, 0, g_r.sA>>>(0);
    inv_hw_k<<<2048, 128, 0, g_r.sA>>>(out, 0);
    inv_d_k<<<dim3(32, 4, 4), 128, 0, g_r.sB>>>(32);
    inv_hw_k<<<2048, 128, 0, g_r.sB>>>(out, 2048);

    // join back to legacy stream
    cudaEventRecord(g_r.eA2, g_r.sA);
    cudaEventRecord(g_r.eB2, g_r.sB);
    cudaStreamWaitEvent(0, g_r.eA2, 0);
    cudaStreamWaitEvent(0, g_r.eB2, 0);
}

// round 16
// speedup vs baseline: 1.0491x; 1.0491x over previous
#include <cuda_runtime.h>
#include <math.h>

#define B 2
#define C 32
#define O 32
#define N 64
#define M 20
#define MM 400
#define MMM 8000
#define NN 4096

// Scratch (bss, allocation-free)
__device__ float g_Y2[(size_t)B * C * N * MM];   // fwd Y2 [bc][d][m]; reused as U1 [bo][d][m]
__device__ float g_Y3[(size_t)B * C * MMM];      // [bc][kd][m]
__device__ float g_Zp[4][(size_t)B * O * MMM];   // 4 c-partial sums of Z

// ---------------------------------------------------------------------------
// Compile-time DCT coefficients (folded to FFMA immediates, rt_SMSP=1)
// ---------------------------------------------------------------------------
__host__ __device__ constexpr double tcos(int a) {      // cos(pi*a/128)
    double x = 3.14159265358979323846264338327950288 * (double)a / 128.0;
    double x2 = x * x, term = 1.0, s = 1.0;
    for (int i = 1; i <= 16; i++) { term *= -x2 / (double)((2 * i - 1) * (2 * i)); s += term; }
    return s;
}
__host__ __device__ constexpr int redu(int k, int n) {
    int a = (k * (2 * n + 1)) % 256;
    return (a > 128) ? 256 - a : a;
}
__host__ __device__ constexpr float CF(int n, int k) {  // forward DCT-II coeff
    double c = tcos(redu(k, n));
    return (k == 0) ? 1.0f : (float)(2.0 * c);
}
__host__ __device__ constexpr float CI(int n, int k) {  // inverse DCT-III coeff
    double c = tcos(redu(k, n));
    return (float)(((k == 0) ? 1.0 : c) / 64.0);
}

template<int I> struct ic { static constexpr int value = I; };
template<int I, int Nn> struct SF {
    template<class F> __device__ __forceinline__ static void run(F&& f) {
        f(ic<I>{}); SF<I + 1, Nn>::run(f);
    }
};
template<int Nn> struct SF<Nn, Nn> {
    template<class F> __device__ __forceinline__ static void run(F&&) {}
};
template<int Nn, class F> __device__ __forceinline__ void static_for(F&& f) { SF<0, Nn>::run(f); }

// cp.async helpers
__device__ __forceinline__ unsigned smem_u32(const void* p) {
    return (unsigned)__cvta_generic_to_shared(p);
}
__device__ __forceinline__ void cp_async16(unsigned dst, const void* src, int szbytes) {
    asm volatile("cp.async.cg.shared.global [%0], [%1], 16, %2;\n"
                 :: "r"(dst), "l"(src), "r"(szbytes));
}
__device__ __forceinline__ void cp_async_wait_all() {
    asm volatile("cp.async.commit_group;\n");
    asm volatile("cp.async.wait_group 0;\n");
}

// ---------------------------------------------------------------------------
// fwd_wh: x[slice][h][w] -> Y2[slice][kh][kw], 1 slice per 128-thread block.
// ---------------------------------------------------------------------------
template<int KW0>
__device__ __forceinline__ void fwd_s1(const float* __restrict__ xr, float* __restrict__ tT, int h) {
    float acc[10];
#pragma unroll
    for (int k = 0; k < 10; k++) acc[k] = 0.f;
    static_for<8>([&](auto W4) {
        constexpr int w4 = W4.value;
        float4 av = *(const float4*)(xr + w4 * 4);
        float4 bv = *(const float4*)(xr + 60 - w4 * 4);
        float s0 = av.x + bv.w, d0 = av.x - bv.w;
        float s1 = av.y + bv.z, d1 = av.y - bv.z;
        float s2 = av.z + bv.y, d2 = av.z - bv.y;
        float s3 = av.w + bv.x, d3 = av.w - bv.x;
        static_for<10>([&](auto K) {
            constexpr int k = K.value;
            constexpr int kw = KW0 + k;
            constexpr float c0 = CF(w4 * 4 + 0, kw);
            constexpr float c1 = CF(w4 * 4 + 1, kw);
            constexpr float c2 = CF(w4 * 4 + 2, kw);
            constexpr float c3 = CF(w4 * 4 + 3, kw);
            if constexpr (kw & 1) {
                acc[k] += d0 * c0; acc[k] += d1 * c1;
                acc[k] += d2 * c2; acc[k] += d3 * c3;
            } else {
                acc[k] += s0 * c0; acc[k] += s1 * c1;
                acc[k] += s2 * c2; acc[k] += s3 * c3;
            }
        });
    });
#pragma unroll
    for (int k = 0; k < 10; k++) tT[(KW0 + k) * 68 + h] = acc[k];
}

template<int KH0>
__device__ __forceinline__ void fwd_s2(const float* __restrict__ trow, float* __restrict__ outp, bool act) {
    float acc[5] = {0.f, 0.f, 0.f, 0.f, 0.f};
    static_for<8>([&](auto H4) {
        constexpr int h4 = H4.value;
        float4 av = *(const float4*)(trow + h4 * 4);
        float4 bv = *(const float4*)(trow + 60 - h4 * 4);
        float s0 = av.x + bv.w, d0 = av.x - bv.w;
        float s1 = av.y + bv.z, d1 = av.y - bv.z;
        float s2 = av.z + bv.y, d2 = av.z - bv.y;
        float s3 = av.w + bv.x, d3 = av.w - bv.x;
        static_for<5>([&](auto K) {
            constexpr int k = K.value;
            constexpr int kh = KH0 + k;
            constexpr float c0 = CF(h4 * 4 + 0, kh);
            constexpr float c1 = CF(h4 * 4 + 1, kh);
            constexpr float c2 = CF(h4 * 4 + 2, kh);
            constexpr float c3 = CF(h4 * 4 + 3, kh);
            if constexpr (kh & 1) {
                acc[k] += d0 * c0; acc[k] += d1 * c1;
                acc[k] += d2 * c2; acc[k] += d3 * c3;
            } else {
                acc[k] += s0 * c0; acc[k] += s1 * c1;
                acc[k] += s2 * c2; acc[k] += s3 * c3;
            }
        });
    });
    if (act) {
#pragma unroll
        for (int k = 0; k < 5; k++) outp[(KH0 + k) * 20] = acc[k];
    }
}

__global__ __launch_bounds__(128) void fwd_wh_k(const float* __restrict__ x, int slice0) {
    __shared__ float xs[64 * 68];         // [h][w], stride 68
    __shared__ float tT[20 * 68];         // [kw][h], stride 68
    int t = threadIdx.x, wid = t >> 5, lane = t & 31;
    int slice = slice0 + blockIdx.x;
    const float* xp = x + (size_t)slice * NN;
#pragma unroll
    for (int r = 0; r < 8; r++) {
        int idx = t + r * 128;            // float4 index 0..1023
        int h = idx >> 4, w4 = idx & 15;
        *(float4*)&xs[h * 68 + w4 * 4] = *(const float4*)(xp + idx * 4);
    }
    __syncthreads();
    {   // stage 1: tT[kw][h] = sum_w xs[h][w]*CF(w,kw)   (butterfly)
        int h = (wid >> 1) * 32 + lane;
        const float* xr = &xs[h * 68];
        if (wid & 1) fwd_s1<10>(xr, tT, h); else fwd_s1<0>(xr, tT, h);
    }
    __syncthreads();
    {   // stage 2: Y2[kh][kw] = sum_h CF(h,kh)*tT[kw][h]  (butterfly, LDS.128)
        bool act = lane < 20;
        int kwc = act ? lane : 0;
        const float* trow = &tT[kwc * 68];
        float* outp = g_Y2 + (size_t)slice * MM + kwc;
        switch (wid) {
            case 0: fwd_s2<0>(trow, outp, act); break;
            case 1: fwd_s2<5>(trow, outp, act); break;
            case 2: fwd_s2<10>(trow, outp, act); break;
            default: fwd_s2<15>(trow, outp, act); break;
        }
    }
}

// ---------------------------------------------------------------------------
// fwd_d: Y2[bc][d][m] -> Y3[bc][kd][m]. Zero-smem, zero-sync, FFMA-imm.
// grid (32 bc, 2 kd-half), block 128 (100 active).
// Thread t owns float4 t of the FULL 400-float m row (t*4 in [0,396]).
// d-butterfly: CF(63-d,kd) = (-1)^kd CF(d,kd).
// ---------------------------------------------------------------------------
template<int KD0>
__device__ __forceinline__ void fwd_d_impl(int bc, int t) {
    const float* src = g_Y2 + (size_t)bc * (N * MM) + t * 4;
    float4 acc[10];
#pragma unroll
    for (int k = 0; k < 10; k++) acc[k] = make_float4(0.f, 0.f, 0.f, 0.f);
    static_for<32>([&](auto D) {
        constexpr int d = D.value;
        float4 a = *(const float4*)(src + (size_t)d * MM);
        float4 b = *(const float4*)(src + (size_t)(63 - d) * MM);
        float4 s, dd;
        s.x = a.x + b.x; s.y = a.y + b.y; s.z = a.z + b.z; s.w = a.w + b.w;
        dd.x = a.x - b.x; dd.y = a.y - b.y; dd.z = a.z - b.z; dd.w = a.w - b.w;
        static_for<10>([&](auto K) {
            constexpr int kd = KD0 + K.value;
            constexpr float c = CF(d, kd);
            float4& t4 = acc[K.value];
            if constexpr (kd & 1) {
                t4.x += dd.x * c; t4.y += dd.y * c; t4.z += dd.z * c; t4.w += dd.w * c;
            } else {
                t4.x += s.x * c; t4.y += s.y * c; t4.z += s.z * c; t4.w += s.w * c;
            }
        });
    });
    float* q = g_Y3 + (size_t)bc * MMM + t * 4;
#pragma unroll
    for (int k = 0; k < 10; k++)
        *(float4*)(q + (size_t)(KD0 + k) * MM) = acc[k];
}

__global__ __launch_bounds__(128) void fwd_d_k(int bc0) {
    int t = threadIdx.x;
    if (t >= 100) return;
    int bc = bc0 + blockIdx.x;
    if (blockIdx.y == 0) fwd_d_impl<0>(bc, t);
    else                 fwd_d_impl<10>(bc, t);
}

// ---------------------------------------------------------------------------
// mix: partial Z over 8 channels per block, cp.async staged, plain stores.
// grid (63 m-tiles of 128, 8 o-tiles of 4, 4 c-quarters), block 128.
// ---------------------------------------------------------------------------
__global__ __launch_bounds__(128) void mix_k(const float* __restrict__ w) {
    __shared__ float ys[2 * 8 * 128];     // 8 KB
    __shared__ float ws[8 * 4 * 128];     // 16 KB
    int mbase = blockIdx.x * 128;
    int o0 = blockIdx.y * 4;
    int c0 = blockIdx.z * 8;
    int t = threadIdx.x, wid = t >> 5, lane = t & 31;
#pragma unroll
    for (int r = 0; r < 4; r++) {         // ys: 512 float4
        int i = t + r * 128;
        int b = i >> 8, c = (i >> 5) & 7, m4 = i & 31;
        int m = mbase + m4 * 4;
        const float* src = g_Y3 + (size_t)(b * C + c0 + c) * MMM + ((m < MMM) ? m : 0);
        cp_async16(smem_u32(&ys[(b * 8 + c) * 128 + m4 * 4]), src, (m < MMM) ? 16 : 0);
    }
#pragma unroll
    for (int r = 0; r < 8; r++) {         // ws: 1024 float4
        int i = t + r * 128;
        int c = i >> 7, ol = (i >> 5) & 3, m4 = i & 31;
        int m = mbase + m4 * 4;
        const float* src = w + ((size_t)(c0 + c) * O + o0 + ol) * MMM + ((m < MMM) ? m : 0);
        cp_async16(smem_u32(&ws[(c * 4 + ol) * 128 + m4 * 4]), src, (m < MMM) ? 16 : 0);
    }
    cp_async_wait_all();
    __syncthreads();
    int o = o0 + wid;
    int m0 = mbase + lane * 4;
    float4 a0 = make_float4(0.f,0.f,0.f,0.f), a1 = a0;
#pragma unroll
    for (int c = 0; c < 8; c++) {
        float4 wv = *(const float4*)&ws[(c * 4 + wid) * 128 + lane * 4];
        float4 y0 = *(const float4*)&ys[c * 128 + lane * 4];
        float4 y1 = *(const float4*)&ys[(8 + c) * 128 + lane * 4];
        a0.x += y0.x*wv.x; a0.y += y0.y*wv.y; a0.z += y0.z*wv.z; a0.w += y0.w*wv.w;
        a1.x += y1.x*wv.x; a1.y += y1.y*wv.y; a1.z += y1.z*wv.z; a1.w += y1.w*wv.w;
    }
    if (m0 < MMM) {
        float* Zp = g_Zp[blockIdx.z];
        *(float4*)(Zp + (size_t)o * MMM + m0) = a0;
        *(float4*)(Zp + (size_t)(O + o) * MMM + m0) = a1;
    }
}

// ---------------------------------------------------------------------------
// inv_d: sum(Zp)[bo][kd][m] -> U1[bo][d][m]. Zero-smem, zero-sync, FFMA-imm.
// grid (32 bo, 4 d-blocks), block 128 (100 active).
// Thread t owns float4 t of the FULL 400-float m row.
// Output-side butterfly: CI(63-d,kd) = (-1)^kd CI(d,kd). Quad-sum inline.
// ---------------------------------------------------------------------------
template<int HB>
__device__ __forceinline__ void inv_d_impl(int bo, int t) {
    size_t base = (size_t)bo * MMM + t * 4;
    const float* p0 = g_Zp[0] + base;
    const float* p1 = g_Zp[1] + base;
    const float* p2 = g_Zp[2] + base;
    const float* p3 = g_Zp[3] + base;
    float4 E[8], Od[8];
#pragma unroll
    for (int i = 0; i < 8; i++) { E[i] = make_float4(0.f,0.f,0.f,0.f); Od[i] = E[i]; }
    static_for<20>([&](auto KD) {
        constexpr int kd = KD.value;
        constexpr size_t off = (size_t)kd * MM;
        float4 v0 = *(const float4*)(p0 + off);
        float4 v1 = *(const float4*)(p1 + off);
        float4 v2 = *(const float4*)(p2 + off);
        float4 v3 = *(const float4*)(p3 + off);
        float4 v;
        v.x = (v0.x + v1.x) + (v2.x + v3.x);
        v.y = (v0.y + v1.y) + (v2.y + v3.y);
        v.z = (v0.z + v1.z) + (v2.z + v3.z);
        v.w = (v0.w + v1.w) + (v2.w + v3.w);
        static_for<8>([&](auto I) {
            constexpr int i = I.value;
            constexpr float c = CI(HB + i, kd);
            if constexpr (kd & 1) {
                Od[i].x += v.x * c; Od[i].y += v.y * c;
                Od[i].z += v.z * c; Od[i].w += v.w * c;
            } else {
                E[i].x += v.x * c; E[i].y += v.y * c;
                E[i].z += v.z * c; E[i].w += v.w * c;
            }
        });
    });
    float* q = g_Y2 + (size_t)bo * (N * MM) + t * 4;
#pragma unroll
    for (int i = 0; i < 8; i++) {
        float4 lo, hi;
        lo.x = E[i].x + Od[i].x; lo.y = E[i].y + Od[i].y;
        lo.z = E[i].z + Od[i].z; lo.w = E[i].w + Od[i].w;
        hi.x = E[i].x - Od[i].x; hi.y = E[i].y - Od[i].y;
        hi.z = E[i].z - Od[i].z; hi.w = E[i].w - Od[i].w;
        *(float4*)(q + (size_t)(HB + i) * MM) = lo;
        *(float4*)(q + (size_t)(63 - HB - i) * MM) = hi;
    }
}

__global__ __launch_bounds__(128) void inv_d_k(int bo0) {
    int t = threadIdx.x;
    if (t >= 100) return;
    int bo = bo0 + blockIdx.x;
    switch (blockIdx.y) {
        case 0: inv_d_impl<0>(bo, t); break;
        case 1: inv_d_impl<8>(bo, t); break;
        case 2: inv_d_impl<16>(bo, t); break;
        default: inv_d_impl<24>(bo, t); break;
    }
}

// ---------------------------------------------------------------------------
// inv_hw: U1[slice][kh][kw] -> out[slice][h][w], 1 slice per 128-thread block.
// tmp stride 28 -> conflict-free LDS.128.
// ---------------------------------------------------------------------------
template<int HB>
__device__ __forceinline__ void inv_s1(const float* __restrict__ zcol, float* __restrict__ tcol, bool act) {
    float E[8], Od[8];
#pragma unroll
    for (int i = 0; i < 8; i++) { E[i] = 0.f; Od[i] = 0.f; }
    static_for<20>([&](auto KH) {
        constexpr int kh = KH.value;
        float zv = zcol[kh * 20];
        static_for<8>([&](auto I) {
            constexpr int i = I.value;
            constexpr float c = CI(HB + i, kh);
            if constexpr (kh & 1) Od[i] += zv * c; else E[i] += zv * c;
        });
    });
    if (act) {
#pragma unroll
        for (int i = 0; i < 8; i++) {
            tcol[(HB + i) * 28] = E[i] + Od[i];
            tcol[(63 - HB - i) * 28] = E[i] - Od[i];
        }
    }
}

template<int W0>
__device__ __forceinline__ void inv_s2(const float* __restrict__ trow, float* __restrict__ orow) {
    float E[16], Od[16];
#pragma unroll
    for (int i = 0; i < 16; i++) { E[i] = 0.f; Od[i] = 0.f; }
    static_for<5>([&](auto K4) {
        constexpr int k4 = K4.value;
        float4 tv = *(const float4*)(trow + k4 * 4);
        float tvv[4] = {tv.x, tv.y, tv.z, tv.w};
        static_for<4>([&](auto J) {
            constexpr int j = J.value;
            constexpr int kw = k4 * 4 + j;
            float tvj = tvv[j];
            static_for<16>([&](auto I) {
                constexpr int i = I.value;
                constexpr float c = CI(W0 + i, kw);
                if constexpr (kw & 1) Od[i] += tvj * c; else E[i] += tvj * c;
            });
        });
    });
#pragma unroll
    for (int j = 0; j < 4; j++) {
        float4 v = make_float4(E[j*4+0] + Od[j*4+0], E[j*4+1] + Od[j*4+1],
                               E[j*4+2] + Od[j*4+2], E[j*4+3] + Od[j*4+3]);
        *(float4*)(orow + W0 + j * 4) = v;
    }
#pragma unroll
    for (int j = 0; j < 4; j++) {
        float4 v = make_float4(E[15-(j*4+0)] - Od[15-(j*4+0)], E[15-(j*4+1)] - Od[15-(j*4+1)],
                               E[15-(j*4+2)] - Od[15-(j*4+2)], E[15-(j*4+3)] - Od[15-(j*4+3)]);
        *(float4*)(orow + (48 - W0) + j * 4) = v;
    }
}

__global__ __launch_bounds__(128) void inv_hw_k(float* __restrict__ out, int slice0) {
    __shared__ float zs[MM];
    __shared__ float tmp[64 * 28];
    int t = threadIdx.x, wid = t >> 5, lane = t & 31;
    int slice = slice0 + blockIdx.x;
    const float* p = g_Y2 + (size_t)slice * MM;
    for (int i = t; i < MM; i += 128) zs[i] = p[i];
    __syncthreads();
    {   // stage 1 (butterfly)
        bool act = lane < 20;
        int kwc = act ? lane : 0;
        const float* zcol = &zs[kwc];
        float* tcol = &tmp[kwc];
        switch (wid) {
            case 0: inv_s1<0>(zcol, tcol, act); break;
            case 1: inv_s1<8>(zcol, tcol, act); break;
            case 2: inv_s1<16>(zcol, tcol, act); break;
            default: inv_s1<24>(zcol, tcol, act); break;
        }
    }
    __syncthreads();
    {   // stage 2 (butterfly), direct gmem stores
        int h = (wid & 1) * 32 + lane;
        const float* trow = &tmp[h * 28];
        float* orow = out + (size_t)slice * NN + h * 64;
        if (wid >> 1) inv_s2<16>(trow, orow); else inv_s2<0>(trow, orow);
    }
}

// ---------------------------------------------------------------------------
// Streams/events created at static init, reused every call.
// ---------------------------------------------------------------------------
struct GraphRes {
    cudaStream_t sA, sB;
    cudaEvent_t eRoot, eB1, eMix, eA2, eB2;
    GraphRes() {
        cudaStreamCreateWithFlags(&sA, cudaStreamNonBlocking);
        cudaStreamCreateWithFlags(&sB, cudaStreamNonBlocking);
        cudaEventCreateWithFlags(&eRoot, cudaEventDisableTiming);
        cudaEventCreateWithFlags(&eB1, cudaEventDisableTiming);
        cudaEventCreateWithFlags(&eMix, cudaEventDisableTiming);
        cudaEventCreateWithFlags(&eA2, cudaEventDisableTiming);
        cudaEventCreateWithFlags(&eB2, cudaEventDisableTiming);
    }
};
static GraphRes g_r;

extern "C" void kernel_launch(void* const* d_in, const int* in_sizes, int n_in,
                              void* d_out, int out_size) {
    const float* x = (const float*)d_in[0];       // (2,32,64,64,64)
    const float* w = (const float*)d_in[1];       // (32,32,20,20,20)
    float* out = (float*)d_out;                   // (2,32,64,64,64)

    // fork from the (captured) legacy stream
    cudaEventRecord(g_r.eRoot, 0);
    cudaStreamWaitEvent(g_r.sA, g_r.eRoot, 0);
    cudaStreamWaitEvent(g_r.sB, g_r.eRoot, 0);

    // forward: two independent bc-halves
    fwd_wh_k<<<2048, 128, 0, g_r.sA>>>(x, 0);
    fwd_d_k<<<dim3(32, 2), 128, 0, g_r.sA>>>(0);
    fwd_wh_k<<<2048, 128, 0, g_r.sB>>>(x, 2048);
    fwd_d_k<<<dim3(32, 2), 128, 0, g_r.sB>>>(32);
    cudaEventRecord(g_r.eB1, g_r.sB);
    cudaStreamWaitEvent(g_r.sA, g_r.eB1, 0);      // join for mix

    mix_k<<<dim3(63, 8, 4), 128, 0, g_r.sA>>>(w);
    cudaEventRecord(g_r.eMix, g_r.sA);
    cudaStreamWaitEvent(g_r.sB, g_r.eMix, 0);

    // inverse: two independent bo-halves (inv_d_B overlaps inv_hw_A)
    inv_d_k<<<dim3(32, 4), 128, 0, g_r.sA>>>(0);
    inv_hw_k<<<2048, 128, 0, g_r.sA>>>(out, 0);
    inv_d_k<<<dim3(32, 4), 128, 0, g_r.sB>>>(32);
    inv_hw_k<<<2048, 128, 0, g_r.sB>>>(out, 2048);

    // join back to legacy stream
    cudaEventRecord(g_r.eA2, g_r.sA);
    cudaEventRecord(g_r.eB2, g_r.sB);
    cudaStreamWaitEvent(0, g_r.eA2, 0);
    cudaStreamWaitEvent(0, g_r.eB2, 0);
}

// round 17
// speedup vs baseline: 1.1137x; 1.0615x over previous
#include <cuda_runtime.h>
#include <math.h>

#define B 2
#define C 32
#define O 32
#define N 64
#define M 20
#define MM 400
#define MMM 8000
#define NN 4096

// Scratch (bss, allocation-free)
__device__ float g_Y2[(size_t)B * C * N * MM];   // fwd Y2 [bc][d][m]; reused as U1 [bo][d][m]
__device__ float g_Y3[(size_t)B * C * MMM];      // [bc][kd][m]
__device__ float g_Zp[4][(size_t)B * O * MMM];   // 4 c-partial sums of Z

// ---------------------------------------------------------------------------
// Compile-time DCT coefficients (folded to FFMA immediates, rt_SMSP=1)
// ---------------------------------------------------------------------------
__host__ __device__ constexpr double tcos(int a) {      // cos(pi*a/128)
    double x = 3.14159265358979323846264338327950288 * (double)a / 128.0;
    double x2 = x * x, term = 1.0, s = 1.0;
    for (int i = 1; i <= 16; i++) { term *= -x2 / (double)((2 * i - 1) * (2 * i)); s += term; }
    return s;
}
__host__ __device__ constexpr int redu(int k, int n) {
    int a = (k * (2 * n + 1)) % 256;
    return (a > 128) ? 256 - a : a;
}
__host__ __device__ constexpr float CF(int n, int k) {  // forward DCT-II coeff
    double c = tcos(redu(k, n));
    return (k == 0) ? 1.0f : (float)(2.0 * c);
}
__host__ __device__ constexpr float CI(int n, int k) {  // inverse DCT-III coeff
    double c = tcos(redu(k, n));
    return (float)(((k == 0) ? 1.0 : c) / 64.0);
}

template<int I> struct ic { static constexpr int value = I; };
template<int I, int Nn> struct SF {
    template<class F> __device__ __forceinline__ static void run(F&& f) {
        f(ic<I>{}); SF<I + 1, Nn>::run(f);
    }
};
template<int Nn> struct SF<Nn, Nn> {
    template<class F> __device__ __forceinline__ static void run(F&&) {}
};
template<int Nn, class F> __device__ __forceinline__ void static_for(F&& f) { SF<0, Nn>::run(f); }

// cp.async helpers
__device__ __forceinline__ unsigned smem_u32(const void* p) {
    return (unsigned)__cvta_generic_to_shared(p);
}
__device__ __forceinline__ void cp_async16(unsigned dst, const void* src, int szbytes) {
    asm volatile("cp.async.cg.shared.global [%0], [%1], 16, %2;\n"
                 :: "r"(dst), "l"(src), "r"(szbytes));
}
__device__ __forceinline__ void cp_async_wait_all() {
    asm volatile("cp.async.commit_group;\n");
    asm volatile("cp.async.wait_group 0;\n");
}

// ---------------------------------------------------------------------------
// fwd_wh: x[slice][h][w] -> Y2[slice][kh][kw], 1 slice per 128-thread block.
// ---------------------------------------------------------------------------
template<int KW0>
__device__ __forceinline__ void fwd_s1(const float* __restrict__ xr, float* __restrict__ tT, int h) {
    float acc[10];
#pragma unroll
    for (int k = 0; k < 10; k++) acc[k] = 0.f;
    static_for<8>([&](auto W4) {
        constexpr int w4 = W4.value;
        float4 av = *(const float4*)(xr + w4 * 4);
        float4 bv = *(const float4*)(xr + 60 - w4 * 4);
        float s0 = av.x + bv.w, d0 = av.x - bv.w;
        float s1 = av.y + bv.z, d1 = av.y - bv.z;
        float s2 = av.z + bv.y, d2 = av.z - bv.y;
        float s3 = av.w + bv.x, d3 = av.w - bv.x;
        static_for<10>([&](auto K) {
            constexpr int k = K.value;
            constexpr int kw = KW0 + k;
            constexpr float c0 = CF(w4 * 4 + 0, kw);
            constexpr float c1 = CF(w4 * 4 + 1, kw);
            constexpr float c2 = CF(w4 * 4 + 2, kw);
            constexpr float c3 = CF(w4 * 4 + 3, kw);
            if constexpr (kw & 1) {
                acc[k] += d0 * c0; acc[k] += d1 * c1;
                acc[k] += d2 * c2; acc[k] += d3 * c3;
            } else {
                acc[k] += s0 * c0; acc[k] += s1 * c1;
                acc[k] += s2 * c2; acc[k] += s3 * c3;
            }
        });
    });
#pragma unroll
    for (int k = 0; k < 10; k++) tT[(KW0 + k) * 68 + h] = acc[k];
}

template<int KH0>
__device__ __forceinline__ void fwd_s2(const float* __restrict__ trow, float* __restrict__ outp, bool act) {
    float acc[5] = {0.f, 0.f, 0.f, 0.f, 0.f};
    static_for<8>([&](auto H4) {
        constexpr int h4 = H4.value;
        float4 av = *(const float4*)(trow + h4 * 4);
        float4 bv = *(const float4*)(trow + 60 - h4 * 4);
        float s0 = av.x + bv.w, d0 = av.x - bv.w;
        float s1 = av.y + bv.z, d1 = av.y - bv.z;
        float s2 = av.z + bv.y, d2 = av.z - bv.y;
        float s3 = av.w + bv.x, d3 = av.w - bv.x;
        static_for<5>([&](auto K) {
            constexpr int k = K.value;
            constexpr int kh = KH0 + k;
            constexpr float c0 = CF(h4 * 4 + 0, kh);
            constexpr float c1 = CF(h4 * 4 + 1, kh);
            constexpr float c2 = CF(h4 * 4 + 2, kh);
            constexpr float c3 = CF(h4 * 4 + 3, kh);
            if constexpr (kh & 1) {
                acc[k] += d0 * c0; acc[k] += d1 * c1;
                acc[k] += d2 * c2; acc[k] += d3 * c3;
            } else {
                acc[k] += s0 * c0; acc[k] += s1 * c1;
                acc[k] += s2 * c2; acc[k] += s3 * c3;
            }
        });
    });
    if (act) {
#pragma unroll
        for (int k = 0; k < 5; k++) outp[(KH0 + k) * 20] = acc[k];
    }
}

__global__ __launch_bounds__(128) void fwd_wh_k(const float* __restrict__ x, int slice0) {
    __shared__ float xs[64 * 68];         // [h][w], stride 68
    __shared__ float tT[20 * 68];         // [kw][h], stride 68
    int t = threadIdx.x, wid = t >> 5, lane = t & 31;
    int slice = slice0 + blockIdx.x;
    const float* xp = x + (size_t)slice * NN;
#pragma unroll
    for (int r = 0; r < 8; r++) {
        int idx = t + r * 128;            // float4 index 0..1023
        int h = idx >> 4, w4 = idx & 15;
        *(float4*)&xs[h * 68 + w4 * 4] = *(const float4*)(xp + idx * 4);
    }
    __syncthreads();
    {   // stage 1: tT[kw][h] = sum_w xs[h][w]*CF(w,kw)   (butterfly)
        int h = (wid >> 1) * 32 + lane;
        const float* xr = &xs[h * 68];
        if (wid & 1) fwd_s1<10>(xr, tT, h); else fwd_s1<0>(xr, tT, h);
    }
    __syncthreads();
    {   // stage 2: Y2[kh][kw] = sum_h CF(h,kh)*tT[kw][h]  (butterfly, LDS.128)
        bool act = lane < 20;
        int kwc = act ? lane : 0;
        const float* trow = &tT[kwc * 68];
        float* outp = g_Y2 + (size_t)slice * MM + kwc;
        switch (wid) {
            case 0: fwd_s2<0>(trow, outp, act); break;
            case 1: fwd_s2<5>(trow, outp, act); break;
            case 2: fwd_s2<10>(trow, outp, act); break;
            default: fwd_s2<15>(trow, outp, act); break;
        }
    }
}

// ---------------------------------------------------------------------------
// fwd_d: Y2[bc][d][m] -> Y3[bc][kd][m]. Scalar-thread, zero-smem, zero-sync.
// grid (32 bc, 4 m-chunks of 100, 2 kd-half), block 100: thread owns ONE m.
// Lanes span consecutive m -> each warp LDG = one 128B line.
// d-butterfly: CF(63-d,kd) = (-1)^kd CF(d,kd).
// ---------------------------------------------------------------------------
template<int KD0>
__device__ __forceinline__ void fwd_d_impl(int bc, int m) {
    const float* src = g_Y2 + (size_t)bc * (N * MM) + m;
    float acc[10];
#pragma unroll
    for (int k = 0; k < 10; k++) acc[k] = 0.f;
    static_for<32>([&](auto D) {
        constexpr int d = D.value;
        float a = src[(size_t)d * MM];
        float b = src[(size_t)(63 - d) * MM];
        float s = a + b, dd = a - b;
        static_for<10>([&](auto K) {
            constexpr int kd = KD0 + K.value;
            constexpr float c = CF(d, kd);
            acc[K.value] += ((kd & 1) ? dd : s) * c;
        });
    });
    float* q = g_Y3 + (size_t)bc * MMM + m;
#pragma unroll
    for (int k = 0; k < 10; k++)
        q[(size_t)(KD0 + k) * MM] = acc[k];
}

__global__ __launch_bounds__(100) void fwd_d_k(int bc0) {
    int m = blockIdx.y * 100 + threadIdx.x;
    int bc = bc0 + blockIdx.x;
    if (blockIdx.z == 0) fwd_d_impl<0>(bc, m);
    else                 fwd_d_impl<10>(bc, m);
}

// ---------------------------------------------------------------------------
// mix: partial Z over 8 channels per block, cp.async staged, plain stores.
// grid (63 m-tiles of 128, 8 o-tiles of 4, 4 c-quarters), block 128.
// ---------------------------------------------------------------------------
__global__ __launch_bounds__(128) void mix_k(const float* __restrict__ w) {
    __shared__ float ys[2 * 8 * 128];     // 8 KB
    __shared__ float ws[8 * 4 * 128];     // 16 KB
    int mbase = blockIdx.x * 128;
    int o0 = blockIdx.y * 4;
    int c0 = blockIdx.z * 8;
    int t = threadIdx.x, wid = t >> 5, lane = t & 31;
#pragma unroll
    for (int r = 0; r < 4; r++) {         // ys: 512 float4
        int i = t + r * 128;
        int b = i >> 8, c = (i >> 5) & 7, m4 = i & 31;
        int m = mbase + m4 * 4;
        const float* src = g_Y3 + (size_t)(b * C + c0 + c) * MMM + ((m < MMM) ? m : 0);
        cp_async16(smem_u32(&ys[(b * 8 + c) * 128 + m4 * 4]), src, (m < MMM) ? 16 : 0);
    }
#pragma unroll
    for (int r = 0; r < 8; r++) {         // ws: 1024 float4
        int i = t + r * 128;
        int c = i >> 7, ol = (i >> 5) & 3, m4 = i & 31;
        int m = mbase + m4 * 4;
        const float* src = w + ((size_t)(c0 + c) * O + o0 + ol) * MMM + ((m < MMM) ? m : 0);
        cp_async16(smem_u32(&ws[(c * 4 + ol) * 128 + m4 * 4]), src, (m < MMM) ? 16 : 0);
    }
    cp_async_wait_all();
    __syncthreads();
    int o = o0 + wid;
    int m0 = mbase + lane * 4;
    float4 a0 = make_float4(0.f,0.f,0.f,0.f), a1 = a0;
#pragma unroll
    for (int c = 0; c < 8; c++) {
        float4 wv = *(const float4*)&ws[(c * 4 + wid) * 128 + lane * 4];
        float4 y0 = *(const float4*)&ys[c * 128 + lane * 4];
        float4 y1 = *(const float4*)&ys[(8 + c) * 128 + lane * 4];
        a0.x += y0.x*wv.x; a0.y += y0.y*wv.y; a0.z += y0.z*wv.z; a0.w += y0.w*wv.w;
        a1.x += y1.x*wv.x; a1.y += y1.y*wv.y; a1.z += y1.z*wv.z; a1.w += y1.w*wv.w;
    }
    if (m0 < MMM) {
        float* Zp = g_Zp[blockIdx.z];
        *(float4*)(Zp + (size_t)o * MMM + m0) = a0;
        *(float4*)(Zp + (size_t)(O + o) * MMM + m0) = a1;
    }
}

// ---------------------------------------------------------------------------
// inv_d: sum(Zp)[bo][kd][m] -> U1[bo][d][m]. Scalar-thread, zero-smem.
// grid (32 bo, 4 m-chunks of 100, 4 d-blocks of 8), block 100.
// Output-side butterfly: CI(63-d,kd) = (-1)^kd CI(d,kd). Quad-sum inline.
// ---------------------------------------------------------------------------
template<int HB>
__device__ __forceinline__ void inv_d_impl(int bo, int m) {
    size_t base = (size_t)bo * MMM + m;
    const float* p0 = g_Zp[0] + base;
    const float* p1 = g_Zp[1] + base;
    const float* p2 = g_Zp[2] + base;
    const float* p3 = g_Zp[3] + base;
    float E[8], Od[8];
#pragma unroll
    for (int i = 0; i < 8; i++) { E[i] = 0.f; Od[i] = 0.f; }
    static_for<20>([&](auto KD) {
        constexpr int kd = KD.value;
        constexpr size_t off = (size_t)kd * MM;
        float v = (p0[off] + p1[off]) + (p2[off] + p3[off]);
        static_for<8>([&](auto I) {
            constexpr int i = I.value;
            constexpr float c = CI(HB + i, kd);
            if constexpr (kd & 1) Od[i] += v * c; else E[i] += v * c;
        });
    });
    float* q = g_Y2 + (size_t)bo * (N * MM) + m;
#pragma unroll
    for (int i = 0; i < 8; i++) {
        q[(size_t)(HB + i) * MM] = E[i] + Od[i];
        q[(size_t)(63 - HB - i) * MM] = E[i] - Od[i];
    }
}

__global__ __launch_bounds__(100) void inv_d_k(int bo0) {
    int m = blockIdx.y * 100 + threadIdx.x;
    int bo = bo0 + blockIdx.x;
    switch (blockIdx.z) {
        case 0: inv_d_impl<0>(bo, m); break;
        case 1: inv_d_impl<8>(bo, m); break;
        case 2: inv_d_impl<16>(bo, m); break;
        default: inv_d_impl<24>(bo, m); break;
    }
}

// ---------------------------------------------------------------------------
// inv_hw: U1[slice][kh][kw] -> out[slice][h][w], 1 slice per 128-thread block.
// tmp stride 28 -> conflict-free LDS.128.
// ---------------------------------------------------------------------------
template<int HB>
__device__ __forceinline__ void inv_s1(const float* __restrict__ zcol, float* __restrict__ tcol, bool act) {
    float E[8], Od[8];
#pragma unroll
    for (int i = 0; i < 8; i++) { E[i] = 0.f; Od[i] = 0.f; }
    static_for<20>([&](auto KH) {
        constexpr int kh = KH.value;
        float zv = zcol[kh * 20];
        static_for<8>([&](auto I) {
            constexpr int i = I.value;
            constexpr float c = CI(HB + i, kh);
            if constexpr (kh & 1) Od[i] += zv * c; else E[i] += zv * c;
        });
    });
    if (act) {
#pragma unroll
        for (int i = 0; i < 8; i++) {
            tcol[(HB + i) * 28] = E[i] + Od[i];
            tcol[(63 - HB - i) * 28] = E[i] - Od[i];
        }
    }
}

template<int W0>
__device__ __forceinline__ void inv_s2(const float* __restrict__ trow, float* __restrict__ orow) {
    float E[16], Od[16];
#pragma unroll
    for (int i = 0; i < 16; i++) { E[i] = 0.f; Od[i] = 0.f; }
    static_for<5>([&](auto K4) {
        constexpr int k4 = K4.value;
        float4 tv = *(const float4*)(trow + k4 * 4);
        float tvv[4] = {tv.x, tv.y, tv.z, tv.w};
        static_for<4>([&](auto J) {
            constexpr int j = J.value;
            constexpr int kw = k4 * 4 + j;
            float tvj = tvv[j];
            static_for<16>([&](auto I) {
                constexpr int i = I.value;
                constexpr float c = CI(W0 + i, kw);
                if constexpr (kw & 1) Od[i] += tvj * c; else E[i] += tvj * c;
            });
        });
    });
#pragma unroll
    for (int j = 0; j < 4; j++) {
        float4 v = make_float4(E[j*4+0] + Od[j*4+0], E[j*4+1] + Od[j*4+1],
                               E[j*4+2] + Od[j*4+2], E[j*4+3] + Od[j*4+3]);
        *(float4*)(orow + W0 + j * 4) = v;
    }
#pragma unroll
    for (int j = 0; j < 4; j++) {
        float4 v = make_float4(E[15-(j*4+0)] - Od[15-(j*4+0)], E[15-(j*4+1)] - Od[15-(j*4+1)],
                               E[15-(j*4+2)] - Od[15-(j*4+2)], E[15-(j*4+3)] - Od[15-(j*4+3)]);
        *(float4*)(orow + (48 - W0) + j * 4) = v;
    }
}

__global__ __launch_bounds__(128) void inv_hw_k(float* __restrict__ out, int slice0) {
    __shared__ float zs[MM];
    __shared__ float tmp[64 * 28];
    int t = threadIdx.x, wid = t >> 5, lane = t & 31;
    int slice = slice0 + blockIdx.x;
    const float* p = g_Y2 + (size_t)slice * MM;
    for (int i = t; i < MM; i += 128) zs[i] = p[i];
    __syncthreads();
    {   // stage 1 (butterfly)
        bool act = lane < 20;
        int kwc = act ? lane : 0;
        const float* zcol = &zs[kwc];
        float* tcol = &tmp[kwc];
        switch (wid) {
            case 0: inv_s1<0>(zcol, tcol, act); break;
            case 1: inv_s1<8>(zcol, tcol, act); break;
            case 2: inv_s1<16>(zcol, tcol, act); break;
            default: inv_s1<24>(zcol, tcol, act); break;
        }
    }
    __syncthreads();
    {   // stage 2 (butterfly), direct gmem stores
        int h = (wid & 1) * 32 + lane;
        const float* trow = &tmp[h * 28];
        float* orow = out + (size_t)slice * NN + h * 64;
        if (wid >> 1) inv_s2<16>(trow, orow); else inv_s2<0>(trow, orow);
    }
}

// ---------------------------------------------------------------------------
// Streams/events created at static init, reused every call.
// ---------------------------------------------------------------------------
struct GraphRes {
    cudaStream_t sA, sB;
    cudaEvent_t eRoot, eB1, eMix, eA2, eB2;
    GraphRes() {
        cudaStreamCreateWithFlags(&sA, cudaStreamNonBlocking);
        cudaStreamCreateWithFlags(&sB, cudaStreamNonBlocking);
        cudaEventCreateWithFlags(&eRoot, cudaEventDisableTiming);
        cudaEventCreateWithFlags(&eB1, cudaEventDisableTiming);
        cudaEventCreateWithFlags(&eMix, cudaEventDisableTiming);
        cudaEventCreateWithFlags(&eA2, cudaEventDisableTiming);
        cudaEventCreateWithFlags(&eB2, cudaEventDisableTiming);
    }
};
static GraphRes g_r;

extern "C" void kernel_launch(void* const* d_in, const int* in_sizes, int n_in,
                              void* d_out, int out_size) {
    const float* x = (const float*)d_in[0];       // (2,32,64,64,64)
    const float* w = (const float*)d_in[1];       // (32,32,20,20,20)
    float* out = (float*)d_out;                   // (2,32,64,64,64)

    // fork from the (captured) legacy stream
    cudaEventRecord(g_r.eRoot, 0);
    cudaStreamWaitEvent(g_r.sA, g_r.eRoot, 0);
    cudaStreamWaitEvent(g_r.sB, g_r.eRoot, 0);

    // forward: two independent bc-halves
    fwd_wh_k<<<2048, 128, 0, g_r.sA>>>(x, 0);
    fwd_d_k<<<dim3(32, 4, 2), 100, 0, g_r.sA>>>(0);
    fwd_wh_k<<<2048, 128, 0, g_r.sB>>>(x, 2048);
    fwd_d_k<<<dim3(32, 4, 2), 100, 0, g_r.sB>>>(32);
    cudaEventRecord(g_r.eB1, g_r.sB);
    cudaStreamWaitEvent(g_r.sA, g_r.eB1, 0);      // join for mix

    mix_k<<<dim3(63, 8, 4), 128, 0, g_r.sA>>>(w);
    cudaEventRecord(g_r.eMix, g_r.sA);
    cudaStreamWaitEvent(g_r.sB, g_r.eMix, 0);

    // inverse: two independent bo-halves (inv_d_B overlaps inv_hw_A)
    inv_d_k<<<dim3(32, 4, 4), 100, 0, g_r.sA>>>(0);
    inv_hw_k<<<2048, 128, 0, g_r.sA>>>(out, 0);
    inv_d_k<<<dim3(32, 4, 4), 100, 0, g_r.sB>>>(32);
    inv_hw_k<<<2048, 128, 0, g_r.sB>>>(out, 2048);

    // join back to legacy stream
    cudaEventRecord(g_r.eA2, g_r.sA);
    cudaEventRecord(g_r.eB2, g_r.sB);
    cudaStreamWaitEvent(0, g_r.eA2, 0);
    cudaStreamWaitEvent(0, g_r.eB2, 0);
}